// round 14
// baseline (speedup 1.0000x reference)
#include <cuda_runtime.h>
#include <cuda_bf16.h>
#include <math.h>

#define TDEC 200
#define TENC 256
#define NB 128
#define NT 1024

// ---------------- device scratch ----------------
__device__ float  d_gipre[(size_t)TDEC * 768 * 64];
__device__ float  d_pmT [(size_t)64 * 256 * 256];     // processed memory [b][d][te]
__device__ float4 d_wA_ih[256 * 256];                 // gate-packed (r,z,n)
__device__ float4 d_wA_hh[256 * 256];
__device__ float4 d_w1_hh[256 * 256];
__device__ float4 d_w2_ih[256 * 256];
__device__ float4 d_w2_hh[256 * 256];
__device__ float4 d_M1  [256 * 512];                  // fused g1_wih@proj_w, .w = proj row
__device__ float  d_m1b [768];                        // g1_wih@proj_b + g1_bih
__device__ float  d_qwT [256 * 256];                  // q_w transposed [k][j]
__device__ float  d_hA[2][256 * 64];                  // ping-pong states [dim][b]
__device__ float  d_hAT[64 * 256];                    // hA new, transposed [b][j]
__device__ float  d_h1[2][256 * 64];
__device__ float  d_h2[2][256 * 64];
__device__ float  d_ctx[256 * 64];
__device__ float  d_d2T[256 * 64];
__device__ float  d_pbuf[(size_t)TDEC * 512 * 64];    // [t][ d3(0:256)|ctx(256:512) ][b]
__device__ unsigned int g_cnt;
__device__ unsigned int g_gen;

__device__ __forceinline__ float tanh_fast(float x) {
    float y; asm("tanh.approx.f32 %0, %1;" : "=f"(y) : "f"(x)); return y;
}
__device__ __forceinline__ float sigmoid_f(float x) {
    return __fdividef(1.f, 1.f + __expf(-x));
}
__device__ __forceinline__ float tanh_f(float x) {
    return __fdividef(2.f, 1.f + __expf(-2.f * x)) - 1.f;
}

// sense-reversing grid barrier (ncu-replay safe)
__device__ __forceinline__ void gbar() {
    __syncthreads();
    __threadfence();   // producer release
    if (threadIdx.x == 0) {
        unsigned int my = *((volatile unsigned int*)&g_gen);
        unsigned int old = atomicInc(&g_cnt, NB - 1);
        if (old == NB - 1) {
            __threadfence();
            atomicAdd(&g_gen, 1u);
        } else {
            while (*((volatile unsigned int*)&g_gen) == my) {}
        }
    }
    __syncthreads();
}

// blocks 0..255: weight packing; blocks 256..767: M1 = g1_wih @ proj_w
__global__ void pack_kernel(const float* att_wih, const float* att_whh,
                            const float* g1_wih, const float* g1_whh,
                            const float* g2_wih, const float* g2_whh,
                            const float* g1_bih, const float* proj_b,
                            const float* q_w, const float* proj_w) {
    int tid = threadIdx.x;
    if (blockIdx.x >= 256) {
        // ---- M1 ----
        __shared__ float wr[768];
        int idx = blockIdx.x - 256;
        int j = idx & 255, half = idx >> 8;
        for (int g = 0; g < 3; g++)
            wr[g*256 + tid] = g1_wih[(size_t)(g*256 + j)*256 + tid];
        __syncthreads();
        int k = half * 256 + tid;
        float ar = 0.f, az = 0.f, an = 0.f;
#pragma unroll 4
        for (int m = 0; m < 256; m++) {
            float p = proj_w[(size_t)m*512 + k];
            ar += wr[m]*p; az += wr[256+m]*p; an += wr[512+m]*p;
        }
        d_M1[(size_t)j*512 + k] = make_float4(ar, az, an, proj_w[(size_t)j*512 + k]);
        return;
    }
    int g = blockIdx.x * 256 + tid;   // [0, 65536)
    int j = g >> 8, k = g & 255;
    d_wA_ih[g] = make_float4(att_wih[(size_t)j*384 + 128 + k],
                             att_wih[(size_t)(256+j)*384 + 128 + k],
                             att_wih[(size_t)(512+j)*384 + 128 + k], 0.f);
    d_wA_hh[g] = make_float4(att_whh[(size_t)j*256 + k],
                             att_whh[(size_t)(256+j)*256 + k],
                             att_whh[(size_t)(512+j)*256 + k], 0.f);
    d_w1_hh[g] = make_float4(g1_whh[(size_t)j*256 + k],
                             g1_whh[(size_t)(256+j)*256 + k],
                             g1_whh[(size_t)(512+j)*256 + k], 0.f);
    d_w2_ih[g] = make_float4(g2_wih[(size_t)j*256 + k],
                             g2_wih[(size_t)(256+j)*256 + k],
                             g2_wih[(size_t)(512+j)*256 + k], 0.f);
    d_w2_hh[g] = make_float4(g2_whh[(size_t)j*256 + k],
                             g2_whh[(size_t)(256+j)*256 + k],
                             g2_whh[(size_t)(512+j)*256 + k], 0.f);
    d_qwT[g] = q_w[(size_t)(g & 255)*256 + (g >> 8)];   // [k][j] <- q_w[j][k]
    if (g < 768) {
        float a = g1_bih[g];
        const float* wr2 = g1_wih + (size_t)g*256;
        for (int m = 0; m < 256; m++) a += wr2[m] * proj_b[m];
        d_m1b[g] = a;
    }
    if (g < 256 * 64) {
        d_hA[0][g] = 0.f; d_hA[1][g] = 0.f;
        d_h1[0][g] = 0.f; d_h1[1][g] = 0.f;
        d_h2[0][g] = 0.f; d_h2[1][g] = 0.f;
        d_ctx[g] = 0.f;
    }
    if (g == 0) { g_cnt = 0u; g_gen = 0u; }
}

__global__ void pm_kernel(const float* __restrict__ enc, const float* __restrict__ mem_w) {
    size_t g = (size_t)blockIdx.x * 256 + threadIdx.x;
    int dd = (int)(g & 255);
    int te = (int)((g >> 8) & 255);
    int bb = (int)(g >> 16);
    const float4* e4 = (const float4*)(enc + ((size_t)bb*256 + te)*256);
    const float4* w4 = (const float4*)(mem_w + (size_t)dd*256);
    float acc = 0.f;
#pragma unroll 8
    for (int k = 0; k < 64; k++) {
        float4 a = e4[k], w = w4[k];
        acc += a.x*w.x + a.y*w.y + a.z*w.z + a.w*w.w;
    }
    d_pmT[((size_t)bb*256 + dd)*256 + te] = acc;
}

__global__ void prenet_kernel(const float* __restrict__ inputs,
                              const float* __restrict__ w1, const float* __restrict__ b1,
                              const float* __restrict__ w2, const float* __restrict__ b2,
                              const float* __restrict__ att_wih,
                              const float* __restrict__ att_bih) {
    int t = blockIdx.x, b = blockIdx.y, tid = threadIdx.x;
    __shared__ float x[160];
    __shared__ float p1[256];
    __shared__ float p2[128];
    if (tid < 160) x[tid] = (t == 0) ? 0.f : inputs[((size_t)b*TDEC + (t-1))*160 + tid];
    __syncthreads();
    {
        float acc = b1[tid];
        const float* wr = w1 + (size_t)tid*160;
#pragma unroll 8
        for (int i = 0; i < 160; i++) acc += wr[i] * x[i];
        p1[tid] = fmaxf(acc, 0.f);
    }
    __syncthreads();
    if (tid < 128) {
        float acc = b2[tid];
        const float* wr = w2 + (size_t)tid*256;
#pragma unroll 8
        for (int i = 0; i < 256; i++) acc += wr[i] * p1[i];
        p2[tid] = fmaxf(acc, 0.f);
    }
    __syncthreads();
    for (int o = tid; o < 768; o += 256) {
        float acc = att_bih[o];
        const float* wr = att_wih + (size_t)o*384;
#pragma unroll 8
        for (int i = 0; i < 128; i++) acc += wr[i] * p2[i];
        d_gipre[((size_t)t*768 + o)*64 + b] = acc;
    }
}

// Split grid: CTAs 0..63 (X): A + SCORECTX; CTAs 64..127 (Y): GRU1'/GRU2 of t-1.
// GRU lane layout (coalescer dedup): lane = [jj(2)|b2lo(3)], warp bits = [kc(3)|b2hi(2)]
//   b2 = b2hi*8 + b2lo ; the 4 jj copies of each activation float2 coalesce to one request.
__global__ void __launch_bounds__(NT, 1)
loop_kernel(const float* __restrict__ enc,
            const int* __restrict__ memlen,
            const float* __restrict__ att_bhh,
            const float* __restrict__ v_w,
            const float* __restrict__ proj_b,
            const float* __restrict__ g1_bhh,
            const float* __restrict__ g2_bih, const float* __restrict__ g2_bhh,
            float* __restrict__ out) {
    extern __shared__ float smem[];
    float4* wb4 = (float4*)smem;              // X: wa_ih[0..1024), wa_hh[1024..2048)
                                              // Y: m1[0..2048), w1hh[2048..3072), w2ih[3072..4096), w2hh[4096..5120)
    float*  vs  = smem + 20480;               // 256 (X only)
    float*  p6  = smem + 20736;               // 16128
    float*  qs  = p6;                         // SCORECTX views
    float*  es  = p6 + 256;
    float*  hs  = p6 + 512;
    float*  ps  = p6 + 768;                   // 1056 (4 x 264)
    float*  red = p6 + 1824;                  // 128
    float*  Ssh = p6 + 1952;                  // 1

    const int tid = threadIdx.x, bid = blockIdx.x;
    const bool isX = bid < 64;
    // dedup mapping
    const int b2 = ((tid >> 5) & 3) * 8 + (tid & 7);   // 0..31 (batch pair)
    const int jj = (tid >> 3) & 3;                     // row within CTA's 4 (lane bits!)
    const int kc = tid >> 7;                           // 0..7
    const int bb = b2 * 2;
    const int fb = tid & 63;                           // finalize (tid<256): batch
    const int fjj = tid >> 6;                          // finalize row 0..3
    const int rbase = (isX ? bid : (bid - 64)) * 4;
    const int jf = rbase + fjj;
    const int mlen = isX ? memlen[bid] : 0;

    // ---- stage weights ----
    if (isX) {
        int src = (rbase + (tid >> 8))*256 + (tid & 255);
        wb4[tid]        = d_wA_ih[src];
        wb4[1024 + tid] = d_wA_hh[src];
        if (tid < 256) vs[tid] = v_w[tid];
    } else {
#pragma unroll
        for (int p = 0; p < 2; p++) {
            int idx = p*1024 + tid;
            wb4[idx] = d_M1[(size_t)(rbase + (idx >> 9))*512 + (idx & 511)];
        }
        int src = (rbase + (tid >> 8))*256 + (tid & 255);
        wb4[2048 + tid] = d_w1_hh[src];
        wb4[3072 + tid] = d_w2_ih[src];
        wb4[4096 + tid] = d_w2_hh[src];
    }
    __syncthreads();

    float* attn_out = out + 2048000;
    float hA_prev = 0.f, h1_prev = 0.f, h2_prev = 0.f, d2T_val = 0.f;

    for (int t = 0; t <= TDEC; t++) {
        // ============ Phase 1: X does A(t) | Y does GRU1'(t-1) ============
        if (isX && t < TDEC) {
            const float* hAo = d_hA[t & 1];
            float* hAn = d_hA[1 - (t & 1)];
            const float4* wi = wb4 + jj*256;
            const float4* wh = wb4 + 1024 + jj*256;
            const float2* c2 = (const float2*)d_ctx;
            const float2* h2v = (const float2*)hAo;
            float irA=0,izA=0,inA=0,hrA=0,hzA=0,hnA=0;
            float irB=0,izB=0,inB=0,hrB=0,hzB=0,hnB=0;
            int k = kc*32;
#pragma unroll
            for (int kk = 0; kk < 32; kk++, k++) {
                float4 a = wi[k]; float2 c = __ldcg(&c2[k*32 + b2]);
                irA += a.x*c.x; izA += a.y*c.x; inA += a.z*c.x;
                irB += a.x*c.y; izB += a.y*c.y; inB += a.z*c.y;
                float4 w = wh[k]; float2 h = __ldcg(&h2v[k*32 + b2]);
                hrA += w.x*h.x; hzA += w.y*h.x; hnA += w.z*h.x;
                hrB += w.x*h.y; hzB += w.y*h.y; hnB += w.z*h.y;
            }
            int ob = jj*6*576 + bb*9 + kc;
            p6[ob + 0*576] = irA; p6[ob + 0*576 + 9] = irB;
            p6[ob + 1*576] = izA; p6[ob + 1*576 + 9] = izB;
            p6[ob + 2*576] = inA; p6[ob + 2*576 + 9] = inB;
            p6[ob + 3*576] = hrA; p6[ob + 3*576 + 9] = hrB;
            p6[ob + 4*576] = hzA; p6[ob + 4*576 + 9] = hzB;
            p6[ob + 5*576] = hnA; p6[ob + 5*576 + 9] = hnB;
            __syncthreads();
            if (tid < 256) {
                float s0=0,s1=0,s2=0,s3=0,s4=0,s5=0;
                int base = fjj*6*576 + fb*9;
#pragma unroll
                for (int q = 0; q < 8; q++) {
                    s0 += p6[base + q];         s1 += p6[base + 576 + q];
                    s2 += p6[base + 1152 + q];  s3 += p6[base + 1728 + q];
                    s4 += p6[base + 2304 + q];  s5 += p6[base + 2880 + q];
                }
                const float* gp = d_gipre + (size_t)t*768*64;
                float gr = s0 + gp[(size_t)jf*64 + fb];
                float gz = s1 + gp[(size_t)(256+jf)*64 + fb];
                float gn = s2 + gp[(size_t)(512+jf)*64 + fb];
                float hr = s3 + att_bhh[jf], hz = s4 + att_bhh[256+jf], hn = s5 + att_bhh[512+jf];
                float r = sigmoid_f(gr + hr), z = sigmoid_f(gz + hz);
                float n = tanh_f(gn + r*hn);
                hA_prev = (1.f - z)*n + z*hA_prev;
                hAn[jf*64 + fb] = hA_prev;
                d_hAT[fb*256 + jf] = hA_prev;
            }
        } else if (!isX && t > 0) {
            const int tm = t - 1;
            const float* hAn_tm = d_hA[1 - (tm & 1)];
            const float* h1o = d_h1[tm & 1];
            float* h1n = d_h1[1 - (tm & 1)];
            const float4* m1 = wb4 + jj*512;
            const float2* hv = (const float2*)h1o;
            const float2* xp = (kc < 4) ? (const float2*)hAn_tm : (const float2*)d_ctx;
            float irA=0,izA=0,inA=0,hrA=0,hzA=0,hnA=0, dtA=0;
            float irB=0,izB=0,inB=0,hrB=0,hzB=0,hnB=0, dtB=0;
            {
                int k = kc*64;
                int kx = (kc < 4) ? k : (k - 256);
#pragma unroll
                for (int i = 0; i < 64; i++, k++, kx++) {
                    float4 a = m1[k]; float2 x = __ldcg(&xp[kx*32 + b2]);
                    irA += a.x*x.x; izA += a.y*x.x; inA += a.z*x.x; dtA += a.w*x.x;
                    irB += a.x*x.y; izB += a.y*x.y; inB += a.z*x.y; dtB += a.w*x.y;
                }
            }
            {
                const float4* wh = wb4 + 2048 + jj*256;
                int k = kc*32;
#pragma unroll
                for (int kk = 0; kk < 32; kk++, k++) {
                    float4 w = wh[k]; float2 h = __ldcg(&hv[k*32 + b2]);
                    hrA += w.x*h.x; hzA += w.y*h.x; hnA += w.z*h.x;
                    hrB += w.x*h.y; hzB += w.y*h.y; hnB += w.z*h.y;
                }
            }
            int ob = jj*7*576 + bb*9 + kc;
            p6[ob + 0*576] = irA; p6[ob + 0*576 + 9] = irB;
            p6[ob + 1*576] = izA; p6[ob + 1*576 + 9] = izB;
            p6[ob + 2*576] = inA; p6[ob + 2*576 + 9] = inB;
            p6[ob + 3*576] = hrA; p6[ob + 3*576 + 9] = hrB;
            p6[ob + 4*576] = hzA; p6[ob + 4*576 + 9] = hzB;
            p6[ob + 5*576] = hnA; p6[ob + 5*576 + 9] = hnB;
            p6[ob + 6*576] = dtA; p6[ob + 6*576 + 9] = dtB;
            __syncthreads();
            if (tid < 256) {
                float s0=0,s1=0,s2=0,s3=0,s4=0,s5=0,s6=0;
                int base = fjj*7*576 + fb*9;
#pragma unroll
                for (int q = 0; q < 8; q++) {
                    s0 += p6[base + q];         s1 += p6[base + 576 + q];
                    s2 += p6[base + 1152 + q];  s3 += p6[base + 1728 + q];
                    s4 += p6[base + 2304 + q];  s5 += p6[base + 2880 + q];
                    s6 += p6[base + 3456 + q];
                }
                float gr = s0 + d_m1b[jf], gz = s1 + d_m1b[256+jf], gn = s2 + d_m1b[512+jf];
                float hr = s3 + g1_bhh[jf], hz = s4 + g1_bhh[256+jf], hn = s5 + g1_bhh[512+jf];
                float dT_val = s6 + proj_b[jf];
                float r = sigmoid_f(gr + hr), z = sigmoid_f(gz + hz);
                float n = tanh_f(gn + r*hn);
                h1_prev = (1.f - z)*n + z*h1_prev;
                h1n[jf*64 + fb] = h1_prev;
                d2T_val = h1_prev + dT_val;
                d_d2T[jf*64 + fb] = d2T_val;
            }
        }
        gbar();

        // ============ Phase 2: X does SCORECTX(t) | Y does GRU2(t-1) ============
        if (isX && t < TDEC) {
            const int b = bid;
            const int lj = tid & 255, lc = tid >> 8;
            if (tid < 256) hs[tid] = __ldcg(&d_hAT[b*256 + tid]);
            __syncthreads();
            {
                const float* qw = d_qwT + (size_t)(lc*64)*256 + lj;
                float acc = 0.f;
                int k = lc*64;
#pragma unroll 8
                for (int i = 0; i < 64; i++, k++)
                    acc += qw[(size_t)i*256] * hs[k];
                ps[lc*264 + lj] = acc;
            }
            __syncthreads();
            if (tid < 256)
                qs[tid] = ps[tid] + ps[264 + tid] + ps[528 + tid] + ps[792 + tid];
            __syncthreads();
            {
                const float* pm = d_pmT + ((size_t)b*256 + lc*64)*256 + lj;
                float acc = 0.f;
                int dd = lc*64;
#pragma unroll 8
                for (int i = 0; i < 64; i++, dd++)
                    acc += vs[dd] * tanh_fast(pm[(size_t)i*256] + qs[dd]);
                ps[lc*264 + lj] = acc;
            }
            __syncthreads();
            if (tid < 256) {
                float s = ps[tid] + ps[264 + tid] + ps[528 + tid] + ps[792 + tid];
                es[tid] = (tid < mlen) ? __expf(s) : 0.f;
            }
            __syncthreads();
            if (tid < 128) red[tid] = es[tid] + es[tid + 128];
            __syncthreads();
            if (tid < 32) {
                float s = red[tid] + red[tid+32] + red[tid+64] + red[tid+96];
#pragma unroll
                for (int off = 16; off; off >>= 1) s += __shfl_down_sync(0xffffffff, s, off);
                if (tid == 0) *Ssh = s;
            }
            __syncthreads();
            float invS = __fdividef(1.f, *Ssh);
            {
                const float* ec = enc + ((size_t)b*256 + lc*64)*256 + lj;
                float acc = 0.f;
                int te = lc*64;
#pragma unroll 8
                for (int i = 0; i < 64; i++, te++)
                    acc += es[te] * ec[(size_t)i*256];
                ps[lc*264 + lj] = acc;
            }
            __syncthreads();
            if (tid < 256) {
                float v = (ps[tid] + ps[264 + tid] + ps[528 + tid] + ps[792 + tid]) * invS;
                d_ctx[tid*64 + b] = v;
                d_pbuf[((size_t)t*512 + 256 + tid)*64 + b] = v;
                attn_out[((size_t)b*TDEC + t)*256 + tid] = es[tid] * invS;
            }
        } else if (!isX && t > 0) {
            const int tm = t - 1;
            const float* h2o = d_h2[tm & 1];
            float* h2n = d_h2[1 - (tm & 1)];
            const float4* wi = wb4 + 3072 + jj*256;
            const float4* wh = wb4 + 4096 + jj*256;
            const float2* x2 = (const float2*)d_d2T;
            const float2* h2v = (const float2*)h2o;
            float irA=0,izA=0,inA=0,hrA=0,hzA=0,hnA=0;
            float irB=0,izB=0,inB=0,hrB=0,hzB=0,hnB=0;
            int k = kc*32;
#pragma unroll
            for (int kk = 0; kk < 32; kk++, k++) {
                float4 a = wi[k]; float2 x = __ldcg(&x2[k*32 + b2]);
                irA += a.x*x.x; izA += a.y*x.x; inA += a.z*x.x;
                irB += a.x*x.y; izB += a.y*x.y; inB += a.z*x.y;
                float4 w = wh[k]; float2 h = __ldcg(&h2v[k*32 + b2]);
                hrA += w.x*h.x; hzA += w.y*h.x; hnA += w.z*h.x;
                hrB += w.x*h.y; hzB += w.y*h.y; hnB += w.z*h.y;
            }
            int ob = jj*6*576 + bb*9 + kc;
            p6[ob + 0*576] = irA; p6[ob + 0*576 + 9] = irB;
            p6[ob + 1*576] = izA; p6[ob + 1*576 + 9] = izB;
            p6[ob + 2*576] = inA; p6[ob + 2*576 + 9] = inB;
            p6[ob + 3*576] = hrA; p6[ob + 3*576 + 9] = hrB;
            p6[ob + 4*576] = hzA; p6[ob + 4*576 + 9] = hzB;
            p6[ob + 5*576] = hnA; p6[ob + 5*576 + 9] = hnB;
            __syncthreads();
            if (tid < 256) {
                float s0=0,s1=0,s2=0,s3=0,s4=0,s5=0;
                int base = fjj*6*576 + fb*9;
#pragma unroll
                for (int q = 0; q < 8; q++) {
                    s0 += p6[base + q];         s1 += p6[base + 576 + q];
                    s2 += p6[base + 1152 + q];  s3 += p6[base + 1728 + q];
                    s4 += p6[base + 2304 + q];  s5 += p6[base + 2880 + q];
                }
                float gr = s0 + g2_bih[jf], gz = s1 + g2_bih[256+jf], gn = s2 + g2_bih[512+jf];
                float hr = s3 + g2_bhh[jf], hz = s4 + g2_bhh[256+jf], hn = s5 + g2_bhh[512+jf];
                float r = sigmoid_f(gr + hr), z = sigmoid_f(gz + hz);
                float n = tanh_f(gn + r*hn);
                h2_prev = (1.f - z)*n + z*h2_prev;
                h2n[jf*64 + fb] = h2_prev;
                d_pbuf[((size_t)tm*512 + jf)*64 + fb] = h2_prev + d2T_val;
            }
        }
        if (t < TDEC) gbar();
    }
}

__global__ void post_kernel(const float* __restrict__ mel_w, const float* __restrict__ mel_b,
                            const float* __restrict__ stop_w, const float* __restrict__ stop_b,
                            float* __restrict__ out) {
    int t = blockIdx.x, tid = threadIdx.x;
    __shared__ __align__(16) float p[512];
    float* stop_out = out + 5324800;
    for (int b = 0; b < 64; b++) {
        __syncthreads();
        p[tid]       = d_pbuf[((size_t)t*512 + tid)*64 + b];
        p[tid + 256] = d_pbuf[((size_t)t*512 + tid + 256)*64 + b];
        __syncthreads();
        if (tid < 160) {
            const float4* w4 = (const float4*)(mel_w + (size_t)tid*512);
            const float4* p4 = (const float4*)p;
            float acc = mel_b[tid];
#pragma unroll 8
            for (int i = 0; i < 128; i++) {
                float4 a = w4[i], x = p4[i];
                acc += a.x*x.x + a.y*x.y + a.z*x.z + a.w*x.w;
            }
            out[((size_t)b*TDEC + t)*160 + tid] = acc;
        } else if (tid == 192) {
            float acc = stop_b[0];
            for (int i = 0; i < 512; i++) acc += stop_w[i] * p[i];
            float s = 1.f / (1.f + expf(-acc));
            stop_out[b*400 + 2*t]     = s;
            stop_out[b*400 + 2*t + 1] = s;
        }
    }
}

extern "C" void kernel_launch(void* const* d_in, const int* in_sizes, int n_in,
                              void* d_out, int out_size) {
    const float* enc      = (const float*)d_in[0];
    const float* inputs   = (const float*)d_in[1];
    const int*   memlen   = (const int*)  d_in[2];
    const float* pre_w1   = (const float*)d_in[3];
    const float* pre_b1   = (const float*)d_in[4];
    const float* pre_w2   = (const float*)d_in[5];
    const float* pre_b2   = (const float*)d_in[6];
    const float* mem_w    = (const float*)d_in[7];
    const float* att_wih  = (const float*)d_in[8];
    const float* att_whh  = (const float*)d_in[9];
    const float* att_bih  = (const float*)d_in[10];
    const float* att_bhh  = (const float*)d_in[11];
    const float* q_w      = (const float*)d_in[12];
    const float* v_w      = (const float*)d_in[13];
    const float* proj_w   = (const float*)d_in[14];
    const float* proj_b   = (const float*)d_in[15];
    const float* g1_wih   = (const float*)d_in[16];
    const float* g1_whh   = (const float*)d_in[17];
    const float* g1_bih   = (const float*)d_in[18];
    const float* g1_bhh   = (const float*)d_in[19];
    const float* g2_wih   = (const float*)d_in[20];
    const float* g2_whh   = (const float*)d_in[21];
    const float* g2_bih   = (const float*)d_in[22];
    const float* g2_bhh   = (const float*)d_in[23];
    const float* mel_w    = (const float*)d_in[24];
    const float* mel_b    = (const float*)d_in[25];
    const float* stop_w   = (const float*)d_in[26];
    const float* stop_b   = (const float*)d_in[27];
    float* out = (float*)d_out;

    int smem_bytes = (20736 + 16128) * (int)sizeof(float);   // 147456 B
    static int smem_set = 0;
    if (!smem_set) {
        cudaFuncSetAttribute(loop_kernel, cudaFuncAttributeMaxDynamicSharedMemorySize,
                             smem_bytes);
        smem_set = 1;
    }

    pack_kernel<<<768, 256>>>(att_wih, att_whh, g1_wih, g1_whh, g2_wih, g2_whh,
                              g1_bih, proj_b, q_w, proj_w);
    pm_kernel<<<16384, 256>>>(enc, mem_w);
    prenet_kernel<<<dim3(TDEC, 64), 256>>>(inputs, pre_w1, pre_b1, pre_w2, pre_b2,
                                           att_wih, att_bih);
    loop_kernel<<<NB, NT, smem_bytes>>>(enc, memlen, att_bhh, v_w, proj_b,
                                        g1_bhh, g2_bih, g2_bhh, out);
    post_kernel<<<TDEC, 256>>>(mel_w, mel_b, stop_w, stop_b, out);
}

// round 16
// speedup vs baseline: 1.0381x; 1.0381x over previous
#include <cuda_runtime.h>
#include <cuda_bf16.h>
#include <math.h>

#define TDEC 200
#define TENC 256

// ---------------- device scratch ----------------
__device__ float  d_gipre[(size_t)TDEC * 768 * 64];
__device__ float  d_pmT [(size_t)64 * 256 * 256];     // processed memory [b][d][te]
__device__ float4 d_wA_ih[256 * 256];                 // gate-packed (r,z,n)
__device__ float4 d_wA_hh[256 * 256];
__device__ float4 d_w1_hh[256 * 256];
__device__ float4 d_w2_ih[256 * 256];
__device__ float4 d_w2_hh[256 * 256];
__device__ float4 d_M1  [256 * 512];                  // fused g1_wih@proj_w, .w = proj row
__device__ float  d_m1b [768];                        // g1_wih@proj_b + g1_bih
__device__ float  d_qwT [256 * 256];                  // q_w transposed [k][j]
__device__ float  d_hA[2][256 * 64];                  // ping-pong states [dim][b]
__device__ float  d_hAT[64 * 256];                    // hA new, transposed [b][j]
__device__ float  d_h1[2][256 * 64];
__device__ float  d_h2[2][256 * 64];
__device__ float  d_ctx[256 * 64];
__device__ float  d_d2T[256 * 64];
__device__ float  d_pbuf[(size_t)TDEC * 512 * 64];    // [t][ d3(0:256)|ctx(256:512) ][b]

__device__ __forceinline__ float tanh_fast(float x) {
    float y; asm("tanh.approx.f32 %0, %1;" : "=f"(y) : "f"(x)); return y;
}
__device__ __forceinline__ float sigmoid_f(float x) {
    return __fdividef(1.f, 1.f + __expf(-x));
}
__device__ __forceinline__ float tanh_f(float x) {
    return __fdividef(2.f, 1.f + __expf(-2.f * x)) - 1.f;
}

// blocks 0..255: weight packing; blocks 256..767: M1 = g1_wih @ proj_w
__global__ void pack_kernel(const float* att_wih, const float* att_whh,
                            const float* g1_wih, const float* g1_whh,
                            const float* g2_wih, const float* g2_whh,
                            const float* g1_bih, const float* proj_b,
                            const float* q_w, const float* proj_w) {
    int tid = threadIdx.x;
    if (blockIdx.x >= 256) {
        __shared__ float wr[768];
        int idx = blockIdx.x - 256;
        int j = idx & 255, half = idx >> 8;
        for (int g = 0; g < 3; g++)
            wr[g*256 + tid] = g1_wih[(size_t)(g*256 + j)*256 + tid];
        __syncthreads();
        int k = half * 256 + tid;
        float ar = 0.f, az = 0.f, an = 0.f;
#pragma unroll 4
        for (int m = 0; m < 256; m++) {
            float p = proj_w[(size_t)m*512 + k];
            ar += wr[m]*p; az += wr[256+m]*p; an += wr[512+m]*p;
        }
        d_M1[(size_t)j*512 + k] = make_float4(ar, az, an, proj_w[(size_t)j*512 + k]);
        return;
    }
    int g = blockIdx.x * 256 + tid;   // [0, 65536)
    int j = g >> 8, k = g & 255;
    d_wA_ih[g] = make_float4(att_wih[(size_t)j*384 + 128 + k],
                             att_wih[(size_t)(256+j)*384 + 128 + k],
                             att_wih[(size_t)(512+j)*384 + 128 + k], 0.f);
    d_wA_hh[g] = make_float4(att_whh[(size_t)j*256 + k],
                             att_whh[(size_t)(256+j)*256 + k],
                             att_whh[(size_t)(512+j)*256 + k], 0.f);
    d_w1_hh[g] = make_float4(g1_whh[(size_t)j*256 + k],
                             g1_whh[(size_t)(256+j)*256 + k],
                             g1_whh[(size_t)(512+j)*256 + k], 0.f);
    d_w2_ih[g] = make_float4(g2_wih[(size_t)j*256 + k],
                             g2_wih[(size_t)(256+j)*256 + k],
                             g2_wih[(size_t)(512+j)*256 + k], 0.f);
    d_w2_hh[g] = make_float4(g2_whh[(size_t)j*256 + k],
                             g2_whh[(size_t)(256+j)*256 + k],
                             g2_whh[(size_t)(512+j)*256 + k], 0.f);
    d_qwT[g] = q_w[(size_t)(g & 255)*256 + (g >> 8)];   // [k][j] <- q_w[j][k]
    if (g < 768) {
        float a = g1_bih[g];
        const float* wr2 = g1_wih + (size_t)g*256;
        for (int m = 0; m < 256; m++) a += wr2[m] * proj_b[m];
        d_m1b[g] = a;
    }
    if (g < 256 * 64) {
        d_hA[0][g] = 0.f; d_hA[1][g] = 0.f;
        d_h1[0][g] = 0.f; d_h1[1][g] = 0.f;
        d_h2[0][g] = 0.f; d_h2[1][g] = 0.f;
        d_ctx[g] = 0.f;
    }
}

__global__ void pm_kernel(const float* __restrict__ enc, const float* __restrict__ mem_w) {
    size_t g = (size_t)blockIdx.x * 256 + threadIdx.x;
    int dd = (int)(g & 255);
    int te = (int)((g >> 8) & 255);
    int bb = (int)(g >> 16);
    const float4* e4 = (const float4*)(enc + ((size_t)bb*256 + te)*256);
    const float4* w4 = (const float4*)(mem_w + (size_t)dd*256);
    float acc = 0.f;
#pragma unroll 8
    for (int k = 0; k < 64; k++) {
        float4 a = e4[k], w = w4[k];
        acc += a.x*w.x + a.y*w.y + a.z*w.z + a.w*w.w;
    }
    d_pmT[((size_t)bb*256 + dd)*256 + te] = acc;
}

__global__ void prenet_kernel(const float* __restrict__ inputs,
                              const float* __restrict__ w1, const float* __restrict__ b1,
                              const float* __restrict__ w2, const float* __restrict__ b2,
                              const float* __restrict__ att_wih,
                              const float* __restrict__ att_bih) {
    int t = blockIdx.x, b = blockIdx.y, tid = threadIdx.x;
    __shared__ float x[160];
    __shared__ float p1[256];
    __shared__ float p2[128];
    if (tid < 160) x[tid] = (t == 0) ? 0.f : inputs[((size_t)b*TDEC + (t-1))*160 + tid];
    __syncthreads();
    {
        float acc = b1[tid];
        const float* wr = w1 + (size_t)tid*160;
#pragma unroll 8
        for (int i = 0; i < 160; i++) acc += wr[i] * x[i];
        p1[tid] = fmaxf(acc, 0.f);
    }
    __syncthreads();
    if (tid < 128) {
        float acc = b2[tid];
        const float* wr = w2 + (size_t)tid*256;
#pragma unroll 8
        for (int i = 0; i < 256; i++) acc += wr[i] * p1[i];
        p2[tid] = fmaxf(acc, 0.f);
    }
    __syncthreads();
    for (int o = tid; o < 768; o += 256) {
        float acc = att_bih[o];
        const float* wr = att_wih + (size_t)o*384;
#pragma unroll 8
        for (int i = 0; i < 128; i++) acc += wr[i] * p2[i];
        d_gipre[((size_t)t*768 + o)*64 + b] = acc;
    }
}

#define SMEM_FLOATS 16128

// Step kernel A: CTAs 0..63 -> attention GRU A(t); CTAs 64..127 -> GRU1'(t-1).
// tid layout: b2 = tid&31, jj = (tid>>5)&3, kc = tid>>7
__global__ void __launch_bounds__(1024, 1)
stepA_kernel(int t,
             const float* __restrict__ att_bhh,
             const float* __restrict__ proj_b,
             const float* __restrict__ g1_bhh) {
    extern __shared__ float p6[];
    const int tid = threadIdx.x, bid = blockIdx.x;
    const bool isX = bid < 64;
    const int b2 = tid & 31;
    const int jj = (tid >> 5) & 3;
    const int kc = tid >> 7;
    const int bb = b2 * 2;
    const int fb = tid & 63;
    const int fjj = tid >> 6;
    const int rbase = (isX ? bid : (bid - 64)) * 4;
    const int jf = rbase + fjj;

    if (isX) {
        if (t >= TDEC) return;
        const float* hAo = d_hA[t & 1];
        float* hAn = d_hA[1 - (t & 1)];
        const float4* wi = d_wA_ih + (rbase + jj)*256;
        const float4* wh = d_wA_hh + (rbase + jj)*256;
        const float2* c2 = (const float2*)d_ctx;
        const float2* h2v = (const float2*)hAo;
        float irA=0,izA=0,inA=0,hrA=0,hzA=0,hnA=0;
        float irB=0,izB=0,inB=0,hrB=0,hzB=0,hnB=0;
        int k = kc*32;
#pragma unroll
        for (int kk = 0; kk < 32; kk++, k++) {
            float4 a = wi[k]; float2 c = c2[k*32 + b2];
            irA += a.x*c.x; izA += a.y*c.x; inA += a.z*c.x;
            irB += a.x*c.y; izB += a.y*c.y; inB += a.z*c.y;
            float4 w = wh[k]; float2 h = h2v[k*32 + b2];
            hrA += w.x*h.x; hzA += w.y*h.x; hnA += w.z*h.x;
            hrB += w.x*h.y; hzB += w.y*h.y; hnB += w.z*h.y;
        }
        int ob = jj*6*576 + bb*9 + kc;
        p6[ob + 0*576] = irA; p6[ob + 0*576 + 9] = irB;
        p6[ob + 1*576] = izA; p6[ob + 1*576 + 9] = izB;
        p6[ob + 2*576] = inA; p6[ob + 2*576 + 9] = inB;
        p6[ob + 3*576] = hrA; p6[ob + 3*576 + 9] = hrB;
        p6[ob + 4*576] = hzA; p6[ob + 4*576 + 9] = hzB;
        p6[ob + 5*576] = hnA; p6[ob + 5*576 + 9] = hnB;
        __syncthreads();
        if (tid < 256) {
            float s0=0,s1=0,s2=0,s3=0,s4=0,s5=0;
            int base = fjj*6*576 + fb*9;
#pragma unroll
            for (int q = 0; q < 8; q++) {
                s0 += p6[base + q];         s1 += p6[base + 576 + q];
                s2 += p6[base + 1152 + q];  s3 += p6[base + 1728 + q];
                s4 += p6[base + 2304 + q];  s5 += p6[base + 2880 + q];
            }
            const float* gp = d_gipre + (size_t)t*768*64;
            float gr = s0 + gp[(size_t)jf*64 + fb];
            float gz = s1 + gp[(size_t)(256+jf)*64 + fb];
            float gn = s2 + gp[(size_t)(512+jf)*64 + fb];
            float hr = s3 + att_bhh[jf], hz = s4 + att_bhh[256+jf], hn = s5 + att_bhh[512+jf];
            float hp = hAo[jf*64 + fb];
            float r = sigmoid_f(gr + hr), z = sigmoid_f(gz + hz);
            float n = tanh_f(gn + r*hn);
            float hv = (1.f - z)*n + z*hp;
            hAn[jf*64 + fb] = hv;
            d_hAT[fb*256 + jf] = hv;
        }
    } else {
        if (t == 0) return;
        const int tm = t - 1;
        const float* hAn_tm = d_hA[1 - (tm & 1)];
        const float* h1o = d_h1[tm & 1];
        float* h1n = d_h1[1 - (tm & 1)];
        const float4* m1 = d_M1 + (size_t)(rbase + jj)*512;
        const float4* wh1 = d_w1_hh + (rbase + jj)*256;
        const float2* hv = (const float2*)h1o;
        const float2* xp = (kc < 4) ? (const float2*)hAn_tm : (const float2*)d_ctx;
        float irA=0,izA=0,inA=0,hrA=0,hzA=0,hnA=0, dtA=0;
        float irB=0,izB=0,inB=0,hrB=0,hzB=0,hnB=0, dtB=0;
        {
            int k = kc*64;
            int kx = (kc < 4) ? k : (k - 256);
#pragma unroll
            for (int i = 0; i < 64; i++, k++, kx++) {
                float4 a = m1[k]; float2 x = xp[kx*32 + b2];
                irA += a.x*x.x; izA += a.y*x.x; inA += a.z*x.x; dtA += a.w*x.x;
                irB += a.x*x.y; izB += a.y*x.y; inB += a.z*x.y; dtB += a.w*x.y;
            }
        }
        {
            int k = kc*32;
#pragma unroll
            for (int kk = 0; kk < 32; kk++, k++) {
                float4 w = wh1[k]; float2 h = hv[k*32 + b2];
                hrA += w.x*h.x; hzA += w.y*h.x; hnA += w.z*h.x;
                hrB += w.x*h.y; hzB += w.y*h.y; hnB += w.z*h.y;
            }
        }
        int ob = jj*7*576 + bb*9 + kc;
        p6[ob + 0*576] = irA; p6[ob + 0*576 + 9] = irB;
        p6[ob + 1*576] = izA; p6[ob + 1*576 + 9] = izB;
        p6[ob + 2*576] = inA; p6[ob + 2*576 + 9] = inB;
        p6[ob + 3*576] = hrA; p6[ob + 3*576 + 9] = hrB;
        p6[ob + 4*576] = hzA; p6[ob + 4*576 + 9] = hzB;
        p6[ob + 5*576] = hnA; p6[ob + 5*576 + 9] = hnB;
        p6[ob + 6*576] = dtA; p6[ob + 6*576 + 9] = dtB;
        __syncthreads();
        if (tid < 256) {
            float s0=0,s1=0,s2=0,s3=0,s4=0,s5=0,s6=0;
            int base = fjj*7*576 + fb*9;
#pragma unroll
            for (int q = 0; q < 8; q++) {
                s0 += p6[base + q];         s1 += p6[base + 576 + q];
                s2 += p6[base + 1152 + q];  s3 += p6[base + 1728 + q];
                s4 += p6[base + 2304 + q];  s5 += p6[base + 2880 + q];
                s6 += p6[base + 3456 + q];
            }
            float gr = s0 + d_m1b[jf], gz = s1 + d_m1b[256+jf], gn = s2 + d_m1b[512+jf];
            float hr = s3 + g1_bhh[jf], hz = s4 + g1_bhh[256+jf], hn = s5 + g1_bhh[512+jf];
            float dT_val = s6 + proj_b[jf];
            float hp = h1o[jf*64 + fb];
            float r = sigmoid_f(gr + hr), z = sigmoid_f(gz + hz);
            float n = tanh_f(gn + r*hn);
            float hv1 = (1.f - z)*n + z*hp;
            h1n[jf*64 + fb] = hv1;
            d_d2T[jf*64 + fb] = hv1 + dT_val;
        }
    }
}

// Step kernel S: CTAs 0..63 -> SCORECTX(t); CTAs 64..127 -> GRU2(t-1).
__global__ void __launch_bounds__(1024, 1)
stepS_kernel(int t,
             const float* __restrict__ enc,
             const int* __restrict__ memlen,
             const float* __restrict__ v_w,
             const float* __restrict__ g2_bih, const float* __restrict__ g2_bhh,
             float* __restrict__ out) {
    extern __shared__ float p6[];
    float* qs  = p6;
    float* es  = p6 + 256;
    float* hs  = p6 + 512;
    float* ps  = p6 + 768;
    float* red = p6 + 1824;
    float* Ssh = p6 + 1952;

    const int tid = threadIdx.x, bid = blockIdx.x;
    const bool isX = bid < 64;
    float* attn_out = out + 2048000;

    if (isX) {
        if (t >= TDEC) return;
        const int b = bid;
        const int mlen = memlen[b];
        const int lj = tid & 255, lc = tid >> 8;
        if (tid < 256) hs[tid] = d_hAT[b*256 + tid];
        __syncthreads();
        {
            const float* qw = d_qwT + (size_t)(lc*64)*256 + lj;
            float acc = 0.f;
            int k = lc*64;
#pragma unroll 8
            for (int i = 0; i < 64; i++, k++)
                acc += qw[(size_t)i*256] * hs[k];
            ps[lc*264 + lj] = acc;
        }
        __syncthreads();
        if (tid < 256)
            qs[tid] = ps[tid] + ps[264 + tid] + ps[528 + tid] + ps[792 + tid];
        __syncthreads();
        {
            const float* pm = d_pmT + ((size_t)b*256 + lc*64)*256 + lj;
            float acc = 0.f;
            int dd = lc*64;
#pragma unroll 8
            for (int i = 0; i < 64; i++, dd++)
                acc += v_w[dd] * tanh_fast(pm[(size_t)i*256] + qs[dd]);
            ps[lc*264 + lj] = acc;
        }
        __syncthreads();
        if (tid < 256) {
            float s = ps[tid] + ps[264 + tid] + ps[528 + tid] + ps[792 + tid];
            es[tid] = (tid < mlen) ? __expf(s) : 0.f;
        }
        __syncthreads();
        if (tid < 128) red[tid] = es[tid] + es[tid + 128];
        __syncthreads();
        if (tid < 32) {
            float s = red[tid] + red[tid+32] + red[tid+64] + red[tid+96];
#pragma unroll
            for (int off = 16; off; off >>= 1) s += __shfl_down_sync(0xffffffff, s, off);
            if (tid == 0) *Ssh = s;
        }
        __syncthreads();
        float invS = __fdividef(1.f, *Ssh);
        {
            const float* ec = enc + ((size_t)b*256 + lc*64)*256 + lj;
            float acc = 0.f;
            int te = lc*64;
#pragma unroll 8
            for (int i = 0; i < 64; i++, te++)
                acc += es[te] * ec[(size_t)i*256];
            ps[lc*264 + lj] = acc;
        }
        __syncthreads();
        if (tid < 256) {
            float v = (ps[tid] + ps[264 + tid] + ps[528 + tid] + ps[792 + tid]) * invS;
            d_ctx[tid*64 + b] = v;
            d_pbuf[((size_t)t*512 + 256 + tid)*64 + b] = v;
            attn_out[((size_t)b*TDEC + t)*256 + tid] = es[tid] * invS;
        }
    } else {
        if (t == 0) return;
        const int tm = t - 1;
        const int b2 = tid & 31;
        const int jj = (tid >> 5) & 3;
        const int kc = tid >> 7;
        const int bb = b2 * 2;
        const int fb = tid & 63;
        const int fjj = tid >> 6;
        const int rbase = (bid - 64) * 4;
        const int jf = rbase + fjj;
        const float* h2o = d_h2[tm & 1];
        float* h2n = d_h2[1 - (tm & 1)];
        const float4* wi = d_w2_ih + (rbase + jj)*256;
        const float4* wh = d_w2_hh + (rbase + jj)*256;
        const float2* x2 = (const float2*)d_d2T;
        const float2* h2v = (const float2*)h2o;
        float irA=0,izA=0,inA=0,hrA=0,hzA=0,hnA=0;
        float irB=0,izB=0,inB=0,hrB=0,hzB=0,hnB=0;
        int k = kc*32;
#pragma unroll
        for (int kk = 0; kk < 32; kk++, k++) {
            float4 a = wi[k]; float2 x = x2[k*32 + b2];
            irA += a.x*x.x; izA += a.y*x.x; inA += a.z*x.x;
            irB += a.x*x.y; izB += a.y*x.y; inB += a.z*x.y;
            float4 w = wh[k]; float2 h = h2v[k*32 + b2];
            hrA += w.x*h.x; hzA += w.y*h.x; hnA += w.z*h.x;
            hrB += w.x*h.y; hzB += w.y*h.y; hnB += w.z*h.y;
        }
        int ob = jj*6*576 + bb*9 + kc;
        p6[ob + 0*576] = irA; p6[ob + 0*576 + 9] = irB;
        p6[ob + 1*576] = izA; p6[ob + 1*576 + 9] = izB;
        p6[ob + 2*576] = inA; p6[ob + 2*576 + 9] = inB;
        p6[ob + 3*576] = hrA; p6[ob + 3*576 + 9] = hrB;
        p6[ob + 4*576] = hzA; p6[ob + 4*576 + 9] = hzB;
        p6[ob + 5*576] = hnA; p6[ob + 5*576 + 9] = hnB;
        __syncthreads();
        if (tid < 256) {
            float s0=0,s1=0,s2=0,s3=0,s4=0,s5=0;
            int base = fjj*6*576 + fb*9;
#pragma unroll
            for (int q = 0; q < 8; q++) {
                s0 += p6[base + q];         s1 += p6[base + 576 + q];
                s2 += p6[base + 1152 + q];  s3 += p6[base + 1728 + q];
                s4 += p6[base + 2304 + q];  s5 += p6[base + 2880 + q];
            }
            float gr = s0 + g2_bih[jf], gz = s1 + g2_bih[256+jf], gn = s2 + g2_bih[512+jf];
            float hr = s3 + g2_bhh[jf], hz = s4 + g2_bhh[256+jf], hn = s5 + g2_bhh[512+jf];
            float hp = h2o[jf*64 + fb];
            float d2v = d_d2T[jf*64 + fb];
            float r = sigmoid_f(gr + hr), z = sigmoid_f(gz + hz);
            float n = tanh_f(gn + r*hn);
            float hv2 = (1.f - z)*n + z*hp;
            h2n[jf*64 + fb] = hv2;
            d_pbuf[((size_t)tm*512 + jf)*64 + fb] = hv2 + d2v;
        }
    }
}

__global__ void post_kernel(const float* __restrict__ mel_w, const float* __restrict__ mel_b,
                            const float* __restrict__ stop_w, const float* __restrict__ stop_b,
                            float* __restrict__ out) {
    int t = blockIdx.x, tid = threadIdx.x;
    __shared__ __align__(16) float p[512];
    float* stop_out = out + 5324800;
    for (int b = 0; b < 64; b++) {
        __syncthreads();
        p[tid]       = d_pbuf[((size_t)t*512 + tid)*64 + b];
        p[tid + 256] = d_pbuf[((size_t)t*512 + tid + 256)*64 + b];
        __syncthreads();
        if (tid < 160) {
            const float4* w4 = (const float4*)(mel_w + (size_t)tid*512);
            const float4* p4 = (const float4*)p;
            float acc = mel_b[tid];
#pragma unroll 8
            for (int i = 0; i < 128; i++) {
                float4 a = w4[i], x = p4[i];
                acc += a.x*x.x + a.y*x.y + a.z*x.z + a.w*x.w;
            }
            out[((size_t)b*TDEC + t)*160 + tid] = acc;
        } else if (tid == 192) {
            float acc = stop_b[0];
            for (int i = 0; i < 512; i++) acc += stop_w[i] * p[i];
            float s = 1.f / (1.f + expf(-acc));
            stop_out[b*400 + 2*t]     = s;
            stop_out[b*400 + 2*t + 1] = s;
        }
    }
}

extern "C" void kernel_launch(void* const* d_in, const int* in_sizes, int n_in,
                              void* d_out, int out_size) {
    const float* enc      = (const float*)d_in[0];
    const float* inputs   = (const float*)d_in[1];
    const int*   memlen   = (const int*)  d_in[2];
    const float* pre_w1   = (const float*)d_in[3];
    const float* pre_b1   = (const float*)d_in[4];
    const float* pre_w2   = (const float*)d_in[5];
    const float* pre_b2   = (const float*)d_in[6];
    const float* mem_w    = (const float*)d_in[7];
    const float* att_wih  = (const float*)d_in[8];
    const float* att_whh  = (const float*)d_in[9];
    const float* att_bih  = (const float*)d_in[10];
    const float* att_bhh  = (const float*)d_in[11];
    const float* q_w      = (const float*)d_in[12];
    const float* v_w      = (const float*)d_in[13];
    const float* proj_w   = (const float*)d_in[14];
    const float* proj_b   = (const float*)d_in[15];
    const float* g1_wih   = (const float*)d_in[16];
    const float* g1_whh   = (const float*)d_in[17];
    const float* g1_bih   = (const float*)d_in[18];
    const float* g1_bhh   = (const float*)d_in[19];
    const float* g2_wih   = (const float*)d_in[20];
    const float* g2_whh   = (const float*)d_in[21];
    const float* g2_bih   = (const float*)d_in[22];
    const float* g2_bhh   = (const float*)d_in[23];
    const float* mel_w    = (const float*)d_in[24];
    const float* mel_b    = (const float*)d_in[25];
    const float* stop_w   = (const float*)d_in[26];
    const float* stop_b   = (const float*)d_in[27];
    float* out = (float*)d_out;

    int smem_bytes = SMEM_FLOATS * (int)sizeof(float);   // 64512 B
    static int smem_set = 0;
    if (!smem_set) {
        cudaFuncSetAttribute(stepA_kernel, cudaFuncAttributeMaxDynamicSharedMemorySize,
                             smem_bytes);
        cudaFuncSetAttribute(stepS_kernel, cudaFuncAttributeMaxDynamicSharedMemorySize,
                             smem_bytes);
        smem_set = 1;
    }

    pack_kernel<<<768, 256>>>(att_wih, att_whh, g1_wih, g1_whh, g2_wih, g2_whh,
                              g1_bih, proj_b, q_w, proj_w);
    pm_kernel<<<16384, 256>>>(enc, mem_w);
    prenet_kernel<<<dim3(TDEC, 64), 256>>>(inputs, pre_w1, pre_b1, pre_w2, pre_b2,
                                           att_wih, att_bih);
    for (int t = 0; t <= TDEC; t++) {
        stepA_kernel<<<128, 1024, smem_bytes>>>(t, att_bhh, proj_b, g1_bhh);
        stepS_kernel<<<128, 1024, smem_bytes>>>(t, enc, memlen, v_w, g2_bih, g2_bhh, out);
    }
    post_kernel<<<TDEC, 256>>>(mel_w, mel_b, stop_w, stop_b, out);
}

// round 17
// speedup vs baseline: 1.0913x; 1.0512x over previous
#include <cuda_runtime.h>
#include <cuda_bf16.h>
#include <math.h>

#define TDEC 200
#define TENC 256

// ---------------- device scratch ----------------
__device__ float  d_gipre[(size_t)TDEC * 768 * 64];
__device__ float  d_pmT [(size_t)64 * 256 * 256];     // processed memory [b][d][te]
__device__ float4 d_wA_ih[256 * 256];                 // gate-packed (r,z,n)
__device__ float4 d_wA_hh[256 * 256];
__device__ float4 d_w1_hh[256 * 256];
__device__ float4 d_w2_ih[256 * 256];
__device__ float4 d_w2_hh[256 * 256];
__device__ float4 d_M1  [256 * 512];                  // fused g1_wih@proj_w, .w = proj row
__device__ float  d_m1b [768];                        // g1_wih@proj_b + g1_bih
__device__ float  d_qwT [256 * 256];                  // q_w transposed [k][j]
__device__ float  d_hA[2][256 * 64];                  // ping-pong states [dim][b]
__device__ float  d_hAT[64 * 256];                    // hA new, transposed [b][j]
__device__ float  d_h1[2][256 * 64];
__device__ float  d_h2[2][256 * 64];
__device__ float  d_ctx[256 * 64];
__device__ float  d_d2T[256 * 64];
__device__ float  d_pbuf[(size_t)TDEC * 512 * 64];    // [t][ d3(0:256)|ctx(256:512) ][b]

__device__ __forceinline__ float tanh_fast(float x) {
    float y; asm("tanh.approx.f32 %0, %1;" : "=f"(y) : "f"(x)); return y;
}
__device__ __forceinline__ float sigmoid_f(float x) {
    return __fdividef(1.f, 1.f + __expf(-x));
}
__device__ __forceinline__ float tanh_f(float x) {
    return __fdividef(2.f, 1.f + __expf(-2.f * x)) - 1.f;
}
__device__ __forceinline__ void cp_async16(void* dst, const void* src) {
    unsigned saddr = (unsigned)__cvta_generic_to_shared(dst);
    asm volatile("cp.async.cg.shared.global [%0], [%1], 16;" :: "r"(saddr), "l"(src) : "memory");
}
#define CP_COMMIT() asm volatile("cp.async.commit_group;" ::: "memory")
#define CP_WAIT0()  asm volatile("cp.async.wait_group 0;" ::: "memory")

// blocks 0..255: weight packing; blocks 256..767: M1 = g1_wih @ proj_w
__global__ void pack_kernel(const float* att_wih, const float* att_whh,
                            const float* g1_wih, const float* g1_whh,
                            const float* g2_wih, const float* g2_whh,
                            const float* g1_bih, const float* proj_b,
                            const float* q_w, const float* proj_w) {
    int tid = threadIdx.x;
    if (blockIdx.x >= 256) {
        __shared__ float wr[768];
        int idx = blockIdx.x - 256;
        int j = idx & 255, half = idx >> 8;
        for (int g = 0; g < 3; g++)
            wr[g*256 + tid] = g1_wih[(size_t)(g*256 + j)*256 + tid];
        __syncthreads();
        int k = half * 256 + tid;
        float ar = 0.f, az = 0.f, an = 0.f;
#pragma unroll 4
        for (int m = 0; m < 256; m++) {
            float p = proj_w[(size_t)m*512 + k];
            ar += wr[m]*p; az += wr[256+m]*p; an += wr[512+m]*p;
        }
        d_M1[(size_t)j*512 + k] = make_float4(ar, az, an, proj_w[(size_t)j*512 + k]);
        return;
    }
    int g = blockIdx.x * 256 + tid;   // [0, 65536)
    int j = g >> 8, k = g & 255;
    d_wA_ih[g] = make_float4(att_wih[(size_t)j*384 + 128 + k],
                             att_wih[(size_t)(256+j)*384 + 128 + k],
                             att_wih[(size_t)(512+j)*384 + 128 + k], 0.f);
    d_wA_hh[g] = make_float4(att_whh[(size_t)j*256 + k],
                             att_whh[(size_t)(256+j)*256 + k],
                             att_whh[(size_t)(512+j)*256 + k], 0.f);
    d_w1_hh[g] = make_float4(g1_whh[(size_t)j*256 + k],
                             g1_whh[(size_t)(256+j)*256 + k],
                             g1_whh[(size_t)(512+j)*256 + k], 0.f);
    d_w2_ih[g] = make_float4(g2_wih[(size_t)j*256 + k],
                             g2_wih[(size_t)(256+j)*256 + k],
                             g2_wih[(size_t)(512+j)*256 + k], 0.f);
    d_w2_hh[g] = make_float4(g2_whh[(size_t)j*256 + k],
                             g2_whh[(size_t)(256+j)*256 + k],
                             g2_whh[(size_t)(512+j)*256 + k], 0.f);
    d_qwT[g] = q_w[(size_t)(g & 255)*256 + (g >> 8)];   // [k][j] <- q_w[j][k]
    if (g < 768) {
        float a = g1_bih[g];
        const float* wr2 = g1_wih + (size_t)g*256;
        for (int m = 0; m < 256; m++) a += wr2[m] * proj_b[m];
        d_m1b[g] = a;
    }
    if (g < 256 * 64) {
        d_hA[0][g] = 0.f; d_hA[1][g] = 0.f;
        d_h1[0][g] = 0.f; d_h1[1][g] = 0.f;
        d_h2[0][g] = 0.f; d_h2[1][g] = 0.f;
        d_ctx[g] = 0.f;
    }
}

__global__ void pm_kernel(const float* __restrict__ enc, const float* __restrict__ mem_w) {
    size_t g = (size_t)blockIdx.x * 256 + threadIdx.x;
    int dd = (int)(g & 255);
    int te = (int)((g >> 8) & 255);
    int bb = (int)(g >> 16);
    const float4* e4 = (const float4*)(enc + ((size_t)bb*256 + te)*256);
    const float4* w4 = (const float4*)(mem_w + (size_t)dd*256);
    float acc = 0.f;
#pragma unroll 8
    for (int k = 0; k < 64; k++) {
        float4 a = e4[k], w = w4[k];
        acc += a.x*w.x + a.y*w.y + a.z*w.z + a.w*w.w;
    }
    d_pmT[((size_t)bb*256 + dd)*256 + te] = acc;
}

__global__ void prenet_kernel(const float* __restrict__ inputs,
                              const float* __restrict__ w1, const float* __restrict__ b1,
                              const float* __restrict__ w2, const float* __restrict__ b2,
                              const float* __restrict__ att_wih,
                              const float* __restrict__ att_bih) {
    int t = blockIdx.x, b = blockIdx.y, tid = threadIdx.x;
    __shared__ float x[160];
    __shared__ float p1[256];
    __shared__ float p2[128];
    if (tid < 160) x[tid] = (t == 0) ? 0.f : inputs[((size_t)b*TDEC + (t-1))*160 + tid];
    __syncthreads();
    {
        float acc = b1[tid];
        const float* wr = w1 + (size_t)tid*160;
#pragma unroll 8
        for (int i = 0; i < 160; i++) acc += wr[i] * x[i];
        p1[tid] = fmaxf(acc, 0.f);
    }
    __syncthreads();
    if (tid < 128) {
        float acc = b2[tid];
        const float* wr = w2 + (size_t)tid*256;
#pragma unroll 8
        for (int i = 0; i < 256; i++) acc += wr[i] * p1[i];
        p2[tid] = fmaxf(acc, 0.f);
    }
    __syncthreads();
    for (int o = tid; o < 768; o += 256) {
        float acc = att_bih[o];
        const float* wr = att_wih + (size_t)o*384;
#pragma unroll 8
        for (int i = 0; i < 128; i++) acc += wr[i] * p2[i];
        d_gipre[((size_t)t*768 + o)*64 + b] = acc;
    }
}

// smem: wbuf (3072 float4 = 48KB) then p6 (16128 floats)
#define STEPA_SMEM (3072*16 + 16128*4)
#define STEPS_SMEM (2048*16 + 16128*4)

// Step kernel A: CTAs 0..63 -> attention GRU A(t); CTAs 64..127 -> GRU1'(t-1).
__global__ void __launch_bounds__(1024, 1)
stepA_kernel(int t,
             const float* __restrict__ att_bhh,
             const float* __restrict__ proj_b,
             const float* __restrict__ g1_bhh) {
    extern __shared__ float smem[];
    float4* wbuf = (float4*)smem;
    float*  p6   = smem + 3072*4;
    const int tid = threadIdx.x, bid = blockIdx.x;
    const bool isX = bid < 64;
    const int b2 = tid & 31;
    const int jj = (tid >> 5) & 3;
    const int kc = tid >> 7;
    const int bb = b2 * 2;
    const int fb = tid & 63;
    const int fjj = tid >> 6;
    const int rbase = (isX ? bid : (bid - 64)) * 4;
    const int jf = rbase + fjj;

    if (isX) {
        if (t >= TDEC) return;
        // stage wA_ih, wA_hh rows
        cp_async16(wbuf + tid,        d_wA_ih + (rbase + (tid >> 8))*256 + (tid & 255));
        cp_async16(wbuf + 1024 + tid, d_wA_hh + (rbase + (tid >> 8))*256 + (tid & 255));
        CP_COMMIT(); CP_WAIT0();
        __syncthreads();

        const float* hAo = d_hA[t & 1];
        float* hAn = d_hA[1 - (t & 1)];
        const float4* wi = wbuf + jj*256;
        const float4* wh = wbuf + 1024 + jj*256;
        const float2* c2 = (const float2*)d_ctx;
        const float2* h2v = (const float2*)hAo;
        float irA=0,izA=0,inA=0,hrA=0,hzA=0,hnA=0;
        float irB=0,izB=0,inB=0,hrB=0,hzB=0,hnB=0;
        int k0 = kc*32;
#pragma unroll
        for (int base = 0; base < 32; base += 8) {
            float2 cv[8], hv[8];
#pragma unroll
            for (int u = 0; u < 8; u++) {
                int k = k0 + base + u;
                cv[u] = c2[k*32 + b2];
                hv[u] = h2v[k*32 + b2];
            }
#pragma unroll
            for (int u = 0; u < 8; u++) {
                int k = k0 + base + u;
                float4 a = wi[k], w = wh[k];
                irA += a.x*cv[u].x; izA += a.y*cv[u].x; inA += a.z*cv[u].x;
                irB += a.x*cv[u].y; izB += a.y*cv[u].y; inB += a.z*cv[u].y;
                hrA += w.x*hv[u].x; hzA += w.y*hv[u].x; hnA += w.z*hv[u].x;
                hrB += w.x*hv[u].y; hzB += w.y*hv[u].y; hnB += w.z*hv[u].y;
            }
        }
        int ob = jj*6*576 + bb*9 + kc;
        p6[ob + 0*576] = irA; p6[ob + 0*576 + 9] = irB;
        p6[ob + 1*576] = izA; p6[ob + 1*576 + 9] = izB;
        p6[ob + 2*576] = inA; p6[ob + 2*576 + 9] = inB;
        p6[ob + 3*576] = hrA; p6[ob + 3*576 + 9] = hrB;
        p6[ob + 4*576] = hzA; p6[ob + 4*576 + 9] = hzB;
        p6[ob + 5*576] = hnA; p6[ob + 5*576 + 9] = hnB;
        __syncthreads();
        if (tid < 256) {
            float s0=0,s1=0,s2=0,s3=0,s4=0,s5=0;
            int base = fjj*6*576 + fb*9;
#pragma unroll
            for (int q = 0; q < 8; q++) {
                s0 += p6[base + q];         s1 += p6[base + 576 + q];
                s2 += p6[base + 1152 + q];  s3 += p6[base + 1728 + q];
                s4 += p6[base + 2304 + q];  s5 += p6[base + 2880 + q];
            }
            const float* gp = d_gipre + (size_t)t*768*64;
            float gr = s0 + gp[(size_t)jf*64 + fb];
            float gz = s1 + gp[(size_t)(256+jf)*64 + fb];
            float gn = s2 + gp[(size_t)(512+jf)*64 + fb];
            float hr = s3 + att_bhh[jf], hz = s4 + att_bhh[256+jf], hn = s5 + att_bhh[512+jf];
            float hp = hAo[jf*64 + fb];
            float r = sigmoid_f(gr + hr), z = sigmoid_f(gz + hz);
            float n = tanh_f(gn + r*hn);
            float hv = (1.f - z)*n + z*hp;
            hAn[jf*64 + fb] = hv;
            d_hAT[fb*256 + jf] = hv;
        }
    } else {
        if (t == 0) return;
        // stage M1 (2048) + w1hh (1024)
        cp_async16(wbuf + tid,        d_M1 + (size_t)(rbase + (tid >> 9))*512 + (tid & 511));
        cp_async16(wbuf + 1024 + tid, d_M1 + (size_t)(rbase + ((tid + 1024) >> 9))*512 + ((tid + 1024) & 511));
        cp_async16(wbuf + 2048 + tid, d_w1_hh + (rbase + (tid >> 8))*256 + (tid & 255));
        CP_COMMIT(); CP_WAIT0();
        __syncthreads();

        const int tm = t - 1;
        const float* hAn_tm = d_hA[1 - (tm & 1)];
        const float* h1o = d_h1[tm & 1];
        float* h1n = d_h1[1 - (tm & 1)];
        const float4* m1 = wbuf + jj*512;
        const float4* wh1 = wbuf + 2048 + jj*256;
        const float2* hv = (const float2*)h1o;
        const float2* xp = (kc < 4) ? (const float2*)hAn_tm : (const float2*)d_ctx;
        float irA=0,izA=0,inA=0,hrA=0,hzA=0,hnA=0, dtA=0;
        float irB=0,izB=0,inB=0,hrB=0,hzB=0,hnB=0, dtB=0;
        {
            int k0 = kc*64;
            int kx0 = (kc < 4) ? k0 : (k0 - 256);
#pragma unroll
            for (int base = 0; base < 64; base += 8) {
                float2 xv[8];
#pragma unroll
                for (int u = 0; u < 8; u++)
                    xv[u] = xp[(kx0 + base + u)*32 + b2];
#pragma unroll
                for (int u = 0; u < 8; u++) {
                    float4 a = m1[k0 + base + u];
                    irA += a.x*xv[u].x; izA += a.y*xv[u].x; inA += a.z*xv[u].x; dtA += a.w*xv[u].x;
                    irB += a.x*xv[u].y; izB += a.y*xv[u].y; inB += a.z*xv[u].y; dtB += a.w*xv[u].y;
                }
            }
        }
        {
            int k0 = kc*32;
#pragma unroll
            for (int base = 0; base < 32; base += 8) {
                float2 hvv[8];
#pragma unroll
                for (int u = 0; u < 8; u++)
                    hvv[u] = hv[(k0 + base + u)*32 + b2];
#pragma unroll
                for (int u = 0; u < 8; u++) {
                    float4 w = wh1[k0 + base + u];
                    hrA += w.x*hvv[u].x; hzA += w.y*hvv[u].x; hnA += w.z*hvv[u].x;
                    hrB += w.x*hvv[u].y; hzB += w.y*hvv[u].y; hnB += w.z*hvv[u].y;
                }
            }
        }
        int ob = jj*7*576 + bb*9 + kc;
        p6[ob + 0*576] = irA; p6[ob + 0*576 + 9] = irB;
        p6[ob + 1*576] = izA; p6[ob + 1*576 + 9] = izB;
        p6[ob + 2*576] = inA; p6[ob + 2*576 + 9] = inB;
        p6[ob + 3*576] = hrA; p6[ob + 3*576 + 9] = hrB;
        p6[ob + 4*576] = hzA; p6[ob + 4*576 + 9] = hzB;
        p6[ob + 5*576] = hnA; p6[ob + 5*576 + 9] = hnB;
        p6[ob + 6*576] = dtA; p6[ob + 6*576 + 9] = dtB;
        __syncthreads();
        if (tid < 256) {
            float s0=0,s1=0,s2=0,s3=0,s4=0,s5=0,s6=0;
            int base = fjj*7*576 + fb*9;
#pragma unroll
            for (int q = 0; q < 8; q++) {
                s0 += p6[base + q];         s1 += p6[base + 576 + q];
                s2 += p6[base + 1152 + q];  s3 += p6[base + 1728 + q];
                s4 += p6[base + 2304 + q];  s5 += p6[base + 2880 + q];
                s6 += p6[base + 3456 + q];
            }
            float gr = s0 + d_m1b[jf], gz = s1 + d_m1b[256+jf], gn = s2 + d_m1b[512+jf];
            float hr = s3 + g1_bhh[jf], hz = s4 + g1_bhh[256+jf], hn = s5 + g1_bhh[512+jf];
            float dT_val = s6 + proj_b[jf];
            float hp = h1o[jf*64 + fb];
            float r = sigmoid_f(gr + hr), z = sigmoid_f(gz + hz);
            float n = tanh_f(gn + r*hn);
            float hv1 = (1.f - z)*n + z*hp;
            h1n[jf*64 + fb] = hv1;
            d_d2T[jf*64 + fb] = hv1 + dT_val;
        }
    }
}

// Step kernel S: CTAs 0..63 -> SCORECTX(t); CTAs 64..127 -> GRU2(t-1).
__global__ void __launch_bounds__(1024, 1)
stepS_kernel(int t,
             const float* __restrict__ enc,
             const int* __restrict__ memlen,
             const float* __restrict__ v_w,
             const float* __restrict__ g2_bih, const float* __restrict__ g2_bhh,
             float* __restrict__ out) {
    extern __shared__ float smem[];
    float4* wbuf = (float4*)smem;
    float*  p6   = smem + 2048*4;
    float* qs  = p6;
    float* es  = p6 + 256;
    float* hs  = p6 + 512;
    float* ps  = p6 + 768;
    float* red = p6 + 1824;
    float* Ssh = p6 + 1952;

    const int tid = threadIdx.x, bid = blockIdx.x;
    const bool isX = bid < 64;
    float* attn_out = out + 2048000;

    if (isX) {
        if (t >= TDEC) return;
        const int b = bid;
        const int mlen = memlen[b];
        const int lj = tid & 255, lc = tid >> 8;
        if (tid < 256) hs[tid] = d_hAT[b*256 + tid];
        __syncthreads();
        // q
        {
            const float* qw = d_qwT + (size_t)(lc*64)*256 + lj;
            float acc = 0.f;
#pragma unroll
            for (int base = 0; base < 64; base += 8) {
                float wv[8];
#pragma unroll
                for (int u = 0; u < 8; u++) wv[u] = qw[(size_t)(base + u)*256];
#pragma unroll
                for (int u = 0; u < 8; u++) acc += wv[u] * hs[lc*64 + base + u];
            }
            ps[lc*264 + lj] = acc;
        }
        __syncthreads();
        if (tid < 256)
            qs[tid] = ps[tid] + ps[264 + tid] + ps[528 + tid] + ps[792 + tid];
        __syncthreads();
        // score
        {
            const float* pm = d_pmT + ((size_t)b*256 + lc*64)*256 + lj;
            float acc = 0.f;
#pragma unroll
            for (int base = 0; base < 64; base += 8) {
                float pv[8];
#pragma unroll
                for (int u = 0; u < 8; u++) pv[u] = pm[(size_t)(base + u)*256];
#pragma unroll
                for (int u = 0; u < 8; u++) {
                    int dd = lc*64 + base + u;
                    acc += v_w[dd] * tanh_fast(pv[u] + qs[dd]);
                }
            }
            ps[lc*264 + lj] = acc;
        }
        __syncthreads();
        if (tid < 256) {
            float s = ps[tid] + ps[264 + tid] + ps[528 + tid] + ps[792 + tid];
            es[tid] = (tid < mlen) ? __expf(s) : 0.f;
        }
        __syncthreads();
        if (tid < 128) red[tid] = es[tid] + es[tid + 128];
        __syncthreads();
        if (tid < 32) {
            float s = red[tid] + red[tid+32] + red[tid+64] + red[tid+96];
#pragma unroll
            for (int off = 16; off; off >>= 1) s += __shfl_down_sync(0xffffffff, s, off);
            if (tid == 0) *Ssh = s;
        }
        __syncthreads();
        float invS = __fdividef(1.f, *Ssh);
        // ctx
        {
            const float* ec = enc + ((size_t)b*256 + lc*64)*256 + lj;
            float acc = 0.f;
#pragma unroll
            for (int base = 0; base < 64; base += 8) {
                float ev[8];
#pragma unroll
                for (int u = 0; u < 8; u++) ev[u] = ec[(size_t)(base + u)*256];
#pragma unroll
                for (int u = 0; u < 8; u++) acc += es[lc*64 + base + u] * ev[u];
            }
            ps[lc*264 + lj] = acc;
        }
        __syncthreads();
        if (tid < 256) {
            float v = (ps[tid] + ps[264 + tid] + ps[528 + tid] + ps[792 + tid]) * invS;
            d_ctx[tid*64 + b] = v;
            d_pbuf[((size_t)t*512 + 256 + tid)*64 + b] = v;
            attn_out[((size_t)b*TDEC + t)*256 + tid] = es[tid] * invS;
        }
    } else {
        if (t == 0) return;
        const int rbase = (bid - 64) * 4;
        // stage w2_ih + w2_hh
        cp_async16(wbuf + tid,        d_w2_ih + (rbase + (tid >> 8))*256 + (tid & 255));
        cp_async16(wbuf + 1024 + tid, d_w2_hh + (rbase + (tid >> 8))*256 + (tid & 255));
        CP_COMMIT(); CP_WAIT0();
        __syncthreads();

        const int tm = t - 1;
        const int b2 = tid & 31;
        const int jj = (tid >> 5) & 3;
        const int kc = tid >> 7;
        const int bb = b2 * 2;
        const int fb = tid & 63;
        const int fjj = tid >> 6;
        const int jf = rbase + fjj;
        const float* h2o = d_h2[tm & 1];
        float* h2n = d_h2[1 - (tm & 1)];
        const float4* wi = wbuf + jj*256;
        const float4* wh = wbuf + 1024 + jj*256;
        const float2* x2 = (const float2*)d_d2T;
        const float2* h2v = (const float2*)h2o;
        float irA=0,izA=0,inA=0,hrA=0,hzA=0,hnA=0;
        float irB=0,izB=0,inB=0,hrB=0,hzB=0,hnB=0;
        int k0 = kc*32;
#pragma unroll
        for (int base = 0; base < 32; base += 8) {
            float2 xv[8], hvv[8];
#pragma unroll
            for (int u = 0; u < 8; u++) {
                int k = k0 + base + u;
                xv[u] = x2[k*32 + b2];
                hvv[u] = h2v[k*32 + b2];
            }
#pragma unroll
            for (int u = 0; u < 8; u++) {
                int k = k0 + base + u;
                float4 a = wi[k], w = wh[k];
                irA += a.x*xv[u].x; izA += a.y*xv[u].x; inA += a.z*xv[u].x;
                irB += a.x*xv[u].y; izB += a.y*xv[u].y; inB += a.z*xv[u].y;
                hrA += w.x*hvv[u].x; hzA += w.y*hvv[u].x; hnA += w.z*hvv[u].x;
                hrB += w.x*hvv[u].y; hzB += w.y*hvv[u].y; hnB += w.z*hvv[u].y;
            }
        }
        int ob = jj*6*576 + bb*9 + kc;
        p6[ob + 0*576] = irA; p6[ob + 0*576 + 9] = irB;
        p6[ob + 1*576] = izA; p6[ob + 1*576 + 9] = izB;
        p6[ob + 2*576] = inA; p6[ob + 2*576 + 9] = inB;
        p6[ob + 3*576] = hrA; p6[ob + 3*576 + 9] = hrB;
        p6[ob + 4*576] = hzA; p6[ob + 4*576 + 9] = hzB;
        p6[ob + 5*576] = hnA; p6[ob + 5*576 + 9] = hnB;
        __syncthreads();
        if (tid < 256) {
            float s0=0,s1=0,s2=0,s3=0,s4=0,s5=0;
            int base = fjj*6*576 + fb*9;
#pragma unroll
            for (int q = 0; q < 8; q++) {
                s0 += p6[base + q];         s1 += p6[base + 576 + q];
                s2 += p6[base + 1152 + q];  s3 += p6[base + 1728 + q];
                s4 += p6[base + 2304 + q];  s5 += p6[base + 2880 + q];
            }
            float gr = s0 + g2_bih[jf], gz = s1 + g2_bih[256+jf], gn = s2 + g2_bih[512+jf];
            float hr = s3 + g2_bhh[jf], hz = s4 + g2_bhh[256+jf], hn = s5 + g2_bhh[512+jf];
            float hp = h2o[jf*64 + fb];
            float d2v = d_d2T[jf*64 + fb];
            float r = sigmoid_f(gr + hr), z = sigmoid_f(gz + hz);
            float n = tanh_f(gn + r*hn);
            float hv2 = (1.f - z)*n + z*hp;
            h2n[jf*64 + fb] = hv2;
            d_pbuf[((size_t)tm*512 + jf)*64 + fb] = hv2 + d2v;
        }
    }
}

__global__ void post_kernel(const float* __restrict__ mel_w, const float* __restrict__ mel_b,
                            const float* __restrict__ stop_w, const float* __restrict__ stop_b,
                            float* __restrict__ out) {
    int t = blockIdx.x, tid = threadIdx.x;
    __shared__ __align__(16) float p[512];
    float* stop_out = out + 5324800;
    for (int b = 0; b < 64; b++) {
        __syncthreads();
        p[tid]       = d_pbuf[((size_t)t*512 + tid)*64 + b];
        p[tid + 256] = d_pbuf[((size_t)t*512 + tid + 256)*64 + b];
        __syncthreads();
        if (tid < 160) {
            const float4* w4 = (const float4*)(mel_w + (size_t)tid*512);
            const float4* p4 = (const float4*)p;
            float acc = mel_b[tid];
#pragma unroll 8
            for (int i = 0; i < 128; i++) {
                float4 a = w4[i], x = p4[i];
                acc += a.x*x.x + a.y*x.y + a.z*x.z + a.w*x.w;
            }
            out[((size_t)b*TDEC + t)*160 + tid] = acc;
        } else if (tid == 192) {
            float acc = stop_b[0];
            for (int i = 0; i < 512; i++) acc += stop_w[i] * p[i];
            float s = 1.f / (1.f + expf(-acc));
            stop_out[b*400 + 2*t]     = s;
            stop_out[b*400 + 2*t + 1] = s;
        }
    }
}

extern "C" void kernel_launch(void* const* d_in, const int* in_sizes, int n_in,
                              void* d_out, int out_size) {
    const float* enc      = (const float*)d_in[0];
    const float* inputs   = (const float*)d_in[1];
    const int*   memlen   = (const int*)  d_in[2];
    const float* pre_w1   = (const float*)d_in[3];
    const float* pre_b1   = (const float*)d_in[4];
    const float* pre_w2   = (const float*)d_in[5];
    const float* pre_b2   = (const float*)d_in[6];
    const float* mem_w    = (const float*)d_in[7];
    const float* att_wih  = (const float*)d_in[8];
    const float* att_whh  = (const float*)d_in[9];
    const float* att_bih  = (const float*)d_in[10];
    const float* att_bhh  = (const float*)d_in[11];
    const float* q_w      = (const float*)d_in[12];
    const float* v_w      = (const float*)d_in[13];
    const float* proj_w   = (const float*)d_in[14];
    const float* proj_b   = (const float*)d_in[15];
    const float* g1_wih   = (const float*)d_in[16];
    const float* g1_whh   = (const float*)d_in[17];
    const float* g1_bih   = (const float*)d_in[18];
    const float* g1_bhh   = (const float*)d_in[19];
    const float* g2_wih   = (const float*)d_in[20];
    const float* g2_whh   = (const float*)d_in[21];
    const float* g2_bih   = (const float*)d_in[22];
    const float* g2_bhh   = (const float*)d_in[23];
    const float* mel_w    = (const float*)d_in[24];
    const float* mel_b    = (const float*)d_in[25];
    const float* stop_w   = (const float*)d_in[26];
    const float* stop_b   = (const float*)d_in[27];
    float* out = (float*)d_out;

    static int smem_set = 0;
    if (!smem_set) {
        cudaFuncSetAttribute(stepA_kernel, cudaFuncAttributeMaxDynamicSharedMemorySize,
                             STEPA_SMEM);
        cudaFuncSetAttribute(stepS_kernel, cudaFuncAttributeMaxDynamicSharedMemorySize,
                             STEPS_SMEM);
        smem_set = 1;
    }

    pack_kernel<<<768, 256>>>(att_wih, att_whh, g1_wih, g1_whh, g2_wih, g2_whh,
                              g1_bih, proj_b, q_w, proj_w);
    pm_kernel<<<16384, 256>>>(enc, mem_w);
    prenet_kernel<<<dim3(TDEC, 64), 256>>>(inputs, pre_w1, pre_b1, pre_w2, pre_b2,
                                           att_wih, att_bih);
    for (int t = 0; t <= TDEC; t++) {
        stepA_kernel<<<128, 1024, STEPA_SMEM>>>(t, att_bhh, proj_b, g1_bhh);
        stepS_kernel<<<128, 1024, STEPS_SMEM>>>(t, enc, memlen, v_w, g2_bih, g2_bhh, out);
    }
    post_kernel<<<TDEC, 256>>>(mel_w, mel_b, stop_w, stop_b, out);
}